// round 7
// baseline (speedup 1.0000x reference)
#include <cuda_runtime.h>
#include <cuda_fp16.h>
#include <cstdint>
#include <cstddef>

#define KP      32832            // 32768 + 64 bias/pad columns
#define KC      32               // K per pipeline chunk
#define NCHUNK  (KP / KC)        // 1026
#define ROWP    40               // smem row pitch in halves (80B, conflict-free)
#define STG_H   (128 * ROWP)     // halves per operand per stage (5120)
#define STAGE_B (2 * STG_H * 2)  // bytes per stage: A + B = 20480
#define SMEM_SZ (4 * STAGE_B)    // 81920

__device__ __align__(1024) __half g_z[(size_t)4096 * KP];   // 257 MiB
__device__ __align__(1024) __half g_w[(size_t)1024 * KP];   //  64 MiB
__device__ float g_gate[4096 * 32];

#define DEV_INLINE __device__ __forceinline__

DEV_INLINE uint32_t smem_u32(const void* p) { return (uint32_t)__cvta_generic_to_shared(p); }

DEV_INLINE void ldsm4(uint32_t* r, uint32_t addr) {
    asm volatile("ldmatrix.sync.aligned.m8n8.x4.shared.b16 {%0,%1,%2,%3}, [%4];"
                 : "=r"(r[0]), "=r"(r[1]), "=r"(r[2]), "=r"(r[3]) : "r"(addr));
}

DEV_INLINE void mma16816(float* c, const uint32_t* a, uint32_t b0, uint32_t b1) {
    asm volatile("mma.sync.aligned.m16n8k16.row.col.f32.f16.f16.f32 "
                 "{%0,%1,%2,%3}, {%4,%5,%6,%7}, {%8,%9}, {%0,%1,%2,%3};"
                 : "+f"(c[0]), "+f"(c[1]), "+f"(c[2]), "+f"(c[3])
                 : "r"(a[0]), "r"(a[1]), "r"(a[2]), "r"(a[3]), "r"(b0), "r"(b1));
}

DEV_INLINE void cp16(uint32_t dst, const void* src) {
    asm volatile("cp.async.cg.shared.global [%0], [%1], 16;" :: "r"(dst), "l"(src));
}

// ---------------------------------------------------------------------------
// K1: gatings = softmax(x @ gw + gb) over 32 leafs.  grid 4096 x 256 thr
// ---------------------------------------------------------------------------
__global__ void k_gate(const float* __restrict__ x, const float* __restrict__ gw,
                       const float* __restrict__ gb) {
    __shared__ float xs[1024];
    __shared__ float part[256];
    int b = blockIdx.x, t = threadIdx.x;
    for (int i = t; i < 1024; i += 256) xs[i] = x[(size_t)b * 1024 + i];
    __syncthreads();
    int l = t & 31, p = t >> 5;
    float s = 0.f;
    #pragma unroll 4
    for (int i = p * 128; i < p * 128 + 128; i++) s += xs[i] * gw[i * 32 + l];
    part[t] = s;
    __syncthreads();
    if (t < 32) {
        float v = gb[t];
        #pragma unroll
        for (int q = 0; q < 8; q++) v += part[q * 32 + t];
        float mx = v;
        for (int o = 16; o; o >>= 1) mx = fmaxf(mx, __shfl_xor_sync(~0u, mx, o));
        float e = __expf(v - mx), se = e;
        for (int o = 16; o; o >>= 1) se += __shfl_xor_sync(~0u, se, o);
        g_gate[b * 32 + t] = e / se;
    }
}

// ---------------------------------------------------------------------------
// K2: W fp16 convert (pw already [o][i][l] = K-major).  grid 32768 x 256
// ---------------------------------------------------------------------------
__global__ void k_wcvt(const float* __restrict__ pw) {
    size_t idx = (size_t)blockIdx.x * 256 + threadIdx.x;   // < 8388608
    size_t s = idx * 4;
    size_t o = s >> 15, k = s & 32767;
    float4 f = ((const float4*)pw)[idx];
    __half2 h0 = __floats2half2_rn(f.x, f.y), h1 = __floats2half2_rn(f.z, f.w);
    uint2 u;
    u.x = *(const uint32_t*)&h0; u.y = *(const uint32_t*)&h1;
    *(uint2*)(g_w + o * KP + k) = u;
}

// K2b: bias columns W[o, 32768+l] = pb[o,l], zero pad.  grid 256 x 256
__global__ void k_wtail(const float* __restrict__ pb) {
    int idx = blockIdx.x * 256 + threadIdx.x;              // < 65536
    int o = idx >> 6, l = idx & 63;
    g_w[(size_t)o * KP + 32768 + l] = __float2half(l < 32 ? pb[o * 32 + l] : 0.f);
}

// ---------------------------------------------------------------------------
// K3: z[b, i*32+l] = x[b,i]*g[b,l]; tail z[b,32768+l]=g[b,l].  grid 4096
// ---------------------------------------------------------------------------
__global__ void k_z(const float* __restrict__ x) {
    __shared__ float gs[32];
    int b = blockIdx.x, t = threadIdx.x;
    if (t < 32) gs[t] = g_gate[b * 32 + t];
    __syncthreads();
    __half* zr = g_z + (size_t)b * KP;
    if (t < 64) zr[32768 + t] = __float2half(t < 32 ? gs[t] : 0.f);
    for (int i = t; i < 1024; i += 256) {
        float xv = x[(size_t)b * 1024 + i];
        __align__(16) __half2 buf[16];
        #pragma unroll
        for (int l = 0; l < 32; l += 2)
            buf[l >> 1] = __floats2half2_rn(xv * gs[l], xv * gs[l + 1]);
        uint4* dst = (uint4*)(zr + (size_t)i * 32);
        const uint4* sb4 = (const uint4*)buf;
        dst[0] = sb4[0]; dst[1] = sb4[1]; dst[2] = sb4[2]; dst[3] = sb4[3];
    }
}

// ---------------------------------------------------------------------------
// K4: GEMM out[4096,1024] = z @ W^T.  Tile 128x128, Kc=32, 4-stage cp.async,
//     ldmatrix + mma.sync.m16n8k16 (fp16 in, fp32 acc).
// ---------------------------------------------------------------------------
DEV_INLINE void load_chunk(const __half* A, const __half* Bm, uint32_t sa, int c, int t) {
    const size_t koff = (size_t)c * KC;
    #pragma unroll
    for (int u = 0; u < 2; u++) {                 // A: 128 rows x 2 x 16B
        int idx = t + u * 256, r = idx >> 2, j = idx & 3;
        cp16(sa + (uint32_t)(r * ROWP + j * 8) * 2, A + (size_t)r * KP + koff + j * 8);
    }
    uint32_t sb = sa + STG_H * 2;
    #pragma unroll
    for (int u = 0; u < 2; u++) {                 // B: 128 rows x 2 x 16B
        int idx = t + u * 256, r = idx >> 2, j = idx & 3;
        cp16(sb + (uint32_t)(r * ROWP + j * 8) * 2, Bm + (size_t)r * KP + koff + j * 8);
    }
}

__global__ void __launch_bounds__(256, 1) k_gemm(float* __restrict__ out) {
    extern __shared__ char smem[];
    const uint32_t sbase = smem_u32(smem);
    const int t = threadIdx.x, w = t >> 5, lane = t & 31;
    const int wm = w & 3, wn = w >> 2;            // warp tile: rows wm*32, cols wn*64

    const int m0 = blockIdx.y * 128, n0 = blockIdx.x * 128;
    const __half* A  = g_z + (size_t)m0 * KP;
    const __half* Bm = g_w + (size_t)n0 * KP;

    float acc[2][8][4];
    #pragma unroll
    for (int i = 0; i < 2; i++)
        #pragma unroll
        for (int j = 0; j < 8; j++)
            #pragma unroll
            for (int q = 0; q < 4; q++) acc[i][j][q] = 0.f;

    // ldmatrix source addresses (row = lane%16, +16B column half for lane>=16)
    const int lrow = lane & 15, lcol = (lane >> 4) * 8;

    #pragma unroll
    for (int c = 0; c < 3; c++) {                 // prologue
        load_chunk(A, Bm, sbase + (uint32_t)c * STAGE_B, c, t);
        asm volatile("cp.async.commit_group;");
    }

    for (int c = 0; c < NCHUNK; c++) {
        asm volatile("cp.async.wait_group 2;");
        __syncthreads();                          // chunk c resident for all threads
        int cn = c + 3;
        if (cn < NCHUNK)
            load_chunk(A, Bm, sbase + (uint32_t)(cn & 3) * STAGE_B, cn, t);
        asm volatile("cp.async.commit_group;");

        uint32_t sA = sbase + (uint32_t)(c & 3) * STAGE_B;
        uint32_t sB = sA + STG_H * 2;
        #pragma unroll
        for (int ks = 0; ks < 2; ks++) {
            const int k0 = ks * 16;
            uint32_t a[2][4], b[4][4];
            #pragma unroll
            for (int mt = 0; mt < 2; mt++)
                ldsm4(a[mt], sA + (uint32_t)((wm * 32 + mt * 16 + lrow) * ROWP + k0 + lcol) * 2);
            #pragma unroll
            for (int q = 0; q < 4; q++)
                ldsm4(b[q], sB + (uint32_t)((wn * 64 + q * 16 + lrow) * ROWP + k0 + lcol) * 2);
            #pragma unroll
            for (int mt = 0; mt < 2; mt++)
                #pragma unroll
                for (int n8 = 0; n8 < 8; n8++) {
                    int q = n8 >> 1, hi = n8 & 1;
                    mma16816(acc[mt][n8], a[mt], b[q][hi], b[q][hi + 2]);
                }
        }
        __syncthreads();                          // compute done before stage reuse
    }

    // Epilogue: c0,c1 -> row lane/4; c2,c3 -> row lane/4+8; cols 2*(lane%4)
    const int rbase = m0 + wm * 32 + (lane >> 2);
    const int cbase = n0 + wn * 64 + (lane & 3) * 2;
    #pragma unroll
    for (int mt = 0; mt < 2; mt++)
        #pragma unroll
        for (int n8 = 0; n8 < 8; n8++) {
            float* p0 = out + (size_t)(rbase + mt * 16) * 1024 + cbase + n8 * 8;
            float* p1 = p0 + 8 * 1024;
            *(float2*)p0 = make_float2(acc[mt][n8][0], acc[mt][n8][1]);
            *(float2*)p1 = make_float2(acc[mt][n8][2], acc[mt][n8][3]);
        }
}

// ---------------------------------------------------------------------------
extern "C" void kernel_launch(void* const* d_in, const int* in_sizes, int n_in,
                              void* d_out, int out_size) {
    const float* x  = (const float*)d_in[0];
    const float* gw = (const float*)d_in[1];
    const float* gb = (const float*)d_in[2];
    const float* pw = (const float*)d_in[3];
    const float* pb = (const float*)d_in[4];
    float* out = (float*)d_out;

    cudaFuncSetAttribute(k_gemm, cudaFuncAttributeMaxDynamicSharedMemorySize, SMEM_SZ);

    k_gate <<<4096, 256>>>(x, gw, gb);
    k_wcvt <<<32768, 256>>>(pw);
    k_wtail<<<256, 256>>>(pb);
    k_z    <<<4096, 256>>>(x);
    k_gemm <<<dim3(8, 32), 256, SMEM_SZ>>>(out);
}